// round 3
// baseline (speedup 1.0000x reference)
#include <cuda_runtime.h>
#include <cstdint>

#define BATCH   65536
#define D0      768
#define D1      512
#define D2      256
#define D3      128
#define NCODES  256
#define NLEVELS 4
#define BETA_F  0.25f
#define QBLOCKS 256

typedef unsigned long long ull;

// ---------------- scratch (no cudaMalloc allowed) ----------------
__device__ float g_h1[(size_t)BATCH * D1];   // 128 MB
__device__ float g_h2[(size_t)BATCH * D2];   //  64 MB
__device__ float g_z [(size_t)BATCH * D3];   //  32 MB
__device__ float g_xq[(size_t)BATCH * D3];   //  32 MB
__device__ float g_loss_part[QBLOCKS];

// ---------------- packed fp32x2 helpers (Blackwell FFMA2) ----------------
#define PACK2(d, lo, hi) \
    asm("mov.b64 %0, {%1, %2};" : "=l"(d) : "f"(lo), "f"(hi))
#define UNPACK2(lo, hi, v) \
    asm("mov.b64 {%0, %1}, %2;" : "=f"(lo), "=f"(hi) : "l"(v))
#define FMA2(d, a, b) \
    asm("fma.rn.f32x2 %0, %1, %2, %0;" : "+l"(d) : "l"(a), "l"(b))
#define FMA2D(d, a, b, c) \
    asm("fma.rn.f32x2 %0, %1, %2, %3;" : "=l"(d) : "l"(a), "l"(b), "l"(c))

// ---------------- tiled fp32 GEMM with FFMA2: C = act(A@W + bias) ----------------
// BM=128, BN=64, BK=16, per-thread 8(M)x4(N) as 4 M-pairs x 4 N, 256 threads.
template <bool RELU>
__global__ __launch_bounds__(256) void sgemm_bias(
    const float* __restrict__ A, const float* __restrict__ W,
    const float* __restrict__ bias, float* __restrict__ C,
    int M, int N, int K)
{
    constexpr int BM = 128, BN = 64, BK = 16;
    __shared__ __align__(16) float As[BK][BM];
    __shared__ __align__(16) float Bs[BK][BN];

    const int tid = threadIdx.x;
    const int tx  = tid & 15;   // col group (16 * 4 -> 64)
    const int ty  = tid >> 4;   // row group (16 * 8 -> 128)
    const int rowBase = blockIdx.y * BM;
    const int colBase = blockIdx.x * BN;

    ull accp[4][4];
#pragma unroll
    for (int i = 0; i < 4; i++)
#pragma unroll
        for (int j = 0; j < 4; j++) accp[i][j] = 0ULL;

    for (int k0 = 0; k0 < K; k0 += BK) {
        // A tile: 128x16 = 512 float4, 2 per thread, stored transposed
#pragma unroll
        for (int t = 0; t < 2; t++) {
            int f  = tid + t * 256;
            int ar = f >> 2;
            int aq = f & 3;
            float4 v = *reinterpret_cast<const float4*>(
                &A[(size_t)(rowBase + ar) * K + k0 + aq * 4]);
            As[aq * 4 + 0][ar] = v.x;
            As[aq * 4 + 1][ar] = v.y;
            As[aq * 4 + 2][ar] = v.z;
            As[aq * 4 + 3][ar] = v.w;
        }
        // B tile: 16x64 = 256 float4, 1 per thread
        {
            int br = tid >> 4;
            int bc = tid & 15;
            float4 v = *reinterpret_cast<const float4*>(
                &W[(size_t)(k0 + br) * N + colBase + bc * 4]);
            *reinterpret_cast<float4*>(&Bs[br][bc * 4]) = v;
        }
        __syncthreads();

#pragma unroll
        for (int kk = 0; kk < BK; kk++) {
            // A pairs along M: rows (ty*8+2i, ty*8+2i+1) contiguous in As
            const ulonglong2* ap16 =
                reinterpret_cast<const ulonglong2*>(&As[kk][ty * 8]);
            ulonglong2 a01 = ap16[0];
            ulonglong2 a23 = ap16[1];
            ull ap[4] = {a01.x, a01.y, a23.x, a23.y};
            float4 b = *reinterpret_cast<const float4*>(&Bs[kk][tx * 4]);
            ull bd[4];
            PACK2(bd[0], b.x, b.x);
            PACK2(bd[1], b.y, b.y);
            PACK2(bd[2], b.z, b.z);
            PACK2(bd[3], b.w, b.w);
#pragma unroll
            for (int i = 0; i < 4; i++) {
                FMA2(accp[i][0], ap[i], bd[0]);
                FMA2(accp[i][1], ap[i], bd[1]);
                FMA2(accp[i][2], ap[i], bd[2]);
                FMA2(accp[i][3], ap[i], bd[3]);
            }
        }
        __syncthreads();
    }

    float4 bv = *reinterpret_cast<const float4*>(&bias[colBase + tx * 4]);
#pragma unroll
    for (int i = 0; i < 4; i++) {
        float e[4], o[4];
        UNPACK2(e[0], o[0], accp[i][0]);
        UNPACK2(e[1], o[1], accp[i][1]);
        UNPACK2(e[2], o[2], accp[i][2]);
        UNPACK2(e[3], o[3], accp[i][3]);
        int r0 = rowBase + ty * 8 + 2 * i;
        float4 v0, v1;
        v0.x = e[0] + bv.x; v0.y = e[1] + bv.y;
        v0.z = e[2] + bv.z; v0.w = e[3] + bv.w;
        v1.x = o[0] + bv.x; v1.y = o[1] + bv.y;
        v1.z = o[2] + bv.z; v1.w = o[3] + bv.w;
        if (RELU) {
            v0.x = fmaxf(v0.x, 0.f); v0.y = fmaxf(v0.y, 0.f);
            v0.z = fmaxf(v0.z, 0.f); v0.w = fmaxf(v0.w, 0.f);
            v1.x = fmaxf(v1.x, 0.f); v1.y = fmaxf(v1.y, 0.f);
            v1.z = fmaxf(v1.z, 0.f); v1.w = fmaxf(v1.w, 0.f);
        }
        *reinterpret_cast<float4*>(&C[(size_t)r0 * N + colBase + tx * 4]) = v0;
        *reinterpret_cast<float4*>(&C[(size_t)(r0 + 1) * N + colBase + tx * 4]) = v1;
    }
}

// ---------------- fused residual quantization: all 4 levels, one kernel ----------------
// One thread = one row. Residual held as 64 f32x2 pairs in registers across
// levels; x_q reconstructed as z - r_final. Codebook chunks streamed via smem.
__global__ __launch_bounds__(256) void quant_all(
    const float* __restrict__ z, const float* __restrict__ codebooks,
    float* __restrict__ xq, float* __restrict__ partials)
{
    __shared__ __align__(16) float sC[64 * D3];  // 32 KB chunk
    __shared__ float snorm[64];
    __shared__ float sred[256];

    const int tid = threadIdx.x;
    const size_t row = (size_t)blockIdx.x * 256 + tid;

    // load residual = z
    ull r2[64];
    {
        const ulonglong2* zp = reinterpret_cast<const ulonglong2*>(z + row * D3);
#pragma unroll
        for (int k = 0; k < 32; k++) {
            ulonglong2 v = zp[k];
            r2[2 * k] = v.x; r2[2 * k + 1] = v.y;
        }
    }
    ull mone; PACK2(mone, -1.0f, -1.0f);
    ull ls0 = 0ULL, ls1 = 0ULL;

    for (int l = 0; l < NLEVELS; l++) {
        const float* C = codebooks + (size_t)l * NCODES * D3;
        float best = 3.4e38f;
        int bi = 0;

        for (int ch = 0; ch < 4; ch++) {
            __syncthreads();
            const float4* src =
                reinterpret_cast<const float4*>(C + (size_t)ch * 64 * D3);
            float4* dst = reinterpret_cast<float4*>(sC);
#pragma unroll
            for (int i = 0; i < 8; i++) dst[tid + i * 256] = src[tid + i * 256];
            __syncthreads();
            if (tid < 64) {
                const float4* cp = reinterpret_cast<const float4*>(sC + tid * D3);
                float s = 0.0f;
#pragma unroll
                for (int i = 0; i < 32; i++) {
                    float4 v = cp[i];
                    s += v.x * v.x + v.y * v.y + v.z * v.z + v.w * v.w;
                }
                snorm[tid] = s;
            }
            __syncthreads();

            for (int c = 0; c < 64; c++) {
                const ulonglong2* cp =
                    reinterpret_cast<const ulonglong2*>(sC + c * D3);
                ull a0 = 0ULL, a1 = 0ULL;
#pragma unroll
                for (int k = 0; k < 32; k++) {
                    ulonglong2 v = cp[k];
                    FMA2(a0, r2[2 * k],     v.x);
                    FMA2(a1, r2[2 * k + 1], v.y);
                }
                float s0, s1, s2, s3;
                UNPACK2(s0, s1, a0);
                UNPACK2(s2, s3, a1);
                float dot = (s0 + s1) + (s2 + s3);
                float score = snorm[c] - 2.0f * dot;
                if (score < best) { best = score; bi = ch * 64 + c; }
            }
        }

        // apply chosen code: d = r - q (new residual), loss += d*d
        const ulonglong2* qp =
            reinterpret_cast<const ulonglong2*>(C + (size_t)bi * D3);
#pragma unroll
        for (int k = 0; k < 32; k++) {
            ulonglong2 q = qp[k];
            ull d0, d1;
            FMA2D(d0, q.x, mone, r2[2 * k]);      // r - q
            FMA2D(d1, q.y, mone, r2[2 * k + 1]);
            FMA2(ls0, d0, d0);
            FMA2(ls1, d1, d1);
            r2[2 * k] = d0; r2[2 * k + 1] = d1;
        }
    }

    // x_q = z - r_final
    {
        const ulonglong2* zp = reinterpret_cast<const ulonglong2*>(z + row * D3);
        ulonglong2* xp = reinterpret_cast<ulonglong2*>(xq + row * D3);
#pragma unroll
        for (int k = 0; k < 32; k++) {
            ulonglong2 v = zp[k];
            ulonglong2 o;
            FMA2D(o.x, r2[2 * k],     mone, v.x);  // z - r
            FMA2D(o.y, r2[2 * k + 1], mone, v.y);
            xp[k] = o;
        }
    }

    float s0, s1, s2, s3;
    UNPACK2(s0, s1, ls0);
    UNPACK2(s2, s3, ls1);
    sred[tid] = (s0 + s1) + (s2 + s3);
    __syncthreads();
#pragma unroll
    for (int s = 128; s > 0; s >>= 1) {
        if (tid < s) sred[tid] += sred[tid + s];
        __syncthreads();
    }
    if (tid == 0) partials[blockIdx.x] = sred[0];
}

// ---------------- deterministic loss finalize ----------------
__global__ void finalize_loss(const float* __restrict__ partials,
                              float* __restrict__ out)
{
    if (threadIdx.x == 0 && blockIdx.x == 0) {
        float tot = 0.0f;
        for (int i = 0; i < QBLOCKS; i++) tot += partials[i];
        float rq = (1.0f + BETA_F) * tot /
                   ((float)NLEVELS * (float)BATCH * (float)D3);
        *out = rq;
    }
}

// ---------------- launch ----------------
extern "C" void kernel_launch(void* const* d_in, const int* in_sizes, int n_in,
                              void* d_out, int out_size)
{
    (void)in_sizes; (void)n_in;
    const float* x   = (const float*)d_in[0];
    const float* ew0 = (const float*)d_in[1];
    const float* eb0 = (const float*)d_in[2];
    const float* ew1 = (const float*)d_in[3];
    const float* eb1 = (const float*)d_in[4];
    const float* ew2 = (const float*)d_in[5];
    const float* eb2 = (const float*)d_in[6];
    const float* dw0 = (const float*)d_in[7];
    const float* db0 = (const float*)d_in[8];
    const float* dw1 = (const float*)d_in[9];
    const float* db1 = (const float*)d_in[10];
    const float* dw2 = (const float*)d_in[11];
    const float* db2 = (const float*)d_in[12];
    const float* cb  = (const float*)d_in[13];
    float* out = (float*)d_out;

    float *h1, *h2, *z, *xq, *lp;
    cudaGetSymbolAddress((void**)&h1, g_h1);
    cudaGetSymbolAddress((void**)&h2, g_h2);
    cudaGetSymbolAddress((void**)&z,  g_z);
    cudaGetSymbolAddress((void**)&xq, g_xq);
    cudaGetSymbolAddress((void**)&lp, g_loss_part);

    const int MB = BATCH / 128;

    // encoder
    sgemm_bias<true ><<<dim3(D1 / 64, MB), 256>>>(x,  ew0, eb0, h1, BATCH, D1, D0);
    sgemm_bias<true ><<<dim3(D2 / 64, MB), 256>>>(h1, ew1, eb1, h2, BATCH, D2, D1);
    sgemm_bias<false><<<dim3(D3 / 64, MB), 256>>>(h2, ew2, eb2, z,  BATCH, D3, D2);

    // fused residual quantization (4 levels, residual in registers)
    quant_all<<<QBLOCKS, 256>>>(z, cb, xq, lp);

    // decoder (y_q == x_q in forward value)
    sgemm_bias<true ><<<dim3(D2 / 64, MB), 256>>>(xq, dw0, db0, h2,  BATCH, D2, D3);
    sgemm_bias<true ><<<dim3(D1 / 64, MB), 256>>>(h2, dw1, db1, h1,  BATCH, D1, D2);
    sgemm_bias<false><<<dim3(D0 / 64, MB), 256>>>(h1, dw2, db2, out, BATCH, D0, D1);

    // scalar rq_loss appended after y
    finalize_loss<<<1, 32>>>(lp, out + (size_t)out_size - 1);
}

// round 6
// speedup vs baseline: 1.1845x; 1.1845x over previous
#include <cuda_runtime.h>
#include <cuda_bf16.h>
#include <cstdint>

#define BATCH   65536
#define D0      768
#define D1      512
#define D2      256
#define D3      128
#define NCODES  256
#define NLEVELS 4
#define BETA_F  0.25f
#define QBLOCKS 256

typedef unsigned long long ull;
typedef __nv_bfloat16 bf16;

// ---------------- scratch (no cudaMalloc allowed) ----------------
__device__ float g_h1[(size_t)BATCH * D1];   // 128 MB
__device__ float g_h2[(size_t)BATCH * D2];   //  64 MB
__device__ float g_z [(size_t)BATCH * D3];   //  32 MB
__device__ float g_xq[(size_t)BATCH * D3];   //  32 MB
__device__ float g_loss_part[QBLOCKS];
// bf16 2-way split decoder weights, transposed to [N][K]
#define WTD_TOTAL 557056
__device__ bf16 g_wb0[WTD_TOTAL];
__device__ bf16 g_wb1[WTD_TOTAL];

// ---------------- helpers ----------------
__device__ __forceinline__ void split2(float v, bf16& h, bf16& m) {
    h = __float2bfloat16_rn(v);
    m = __float2bfloat16_rn(v - __bfloat162float(h));
}
__device__ __forceinline__ void mma_bf16(float* c, const uint32_t* a,
                                         const uint32_t* b) {
    asm volatile(
        "mma.sync.aligned.m16n8k16.row.col.f32.bf16.bf16.f32 "
        "{%0,%1,%2,%3}, {%4,%5,%6,%7}, {%8,%9}, {%0,%1,%2,%3};"
        : "+f"(c[0]), "+f"(c[1]), "+f"(c[2]), "+f"(c[3])
        : "r"(a[0]), "r"(a[1]), "r"(a[2]), "r"(a[3]), "r"(b[0]), "r"(b[1]));
}

// packed fp32x2 (quant kernel)
#define PACK2(d, lo, hi) \
    asm("mov.b64 %0, {%1, %2};" : "=l"(d) : "f"(lo), "f"(hi))
#define UNPACK2(lo, hi, v) \
    asm("mov.b64 {%0, %1}, %2;" : "=f"(lo), "=f"(hi) : "l"(v))
#define FMA2(d, a, b) \
    asm("fma.rn.f32x2 %0, %1, %2, %0;" : "+l"(d) : "l"(a), "l"(b))
#define FMA2D(d, a, b, c) \
    asm("fma.rn.f32x2 %0, %1, %2, %3;" : "=l"(d) : "l"(a), "l"(b), "l"(c))

// ---------------- scalar fp32 GEMM (encoder; flip-safe, proven R1) ---------
template <bool RELU>
__global__ __launch_bounds__(256) void sgemm_bias(
    const float* __restrict__ A, const float* __restrict__ W,
    const float* __restrict__ bias, float* __restrict__ C,
    int M, int N, int K)
{
    constexpr int BM = 128, BN = 64, BK = 16, TM = 8, TN = 4;
    __shared__ __align__(16) float As[BK][BM];
    __shared__ __align__(16) float Bs[BK][BN];

    const int tid = threadIdx.x;
    const int tx  = tid & 15;
    const int ty  = tid >> 4;
    const int rowBase = blockIdx.y * BM;
    const int colBase = blockIdx.x * BN;

    float acc[TM][TN];
#pragma unroll
    for (int i = 0; i < TM; i++)
#pragma unroll
        for (int j = 0; j < TN; j++) acc[i][j] = 0.0f;

    for (int k0 = 0; k0 < K; k0 += BK) {
#pragma unroll
        for (int t = 0; t < 2; t++) {
            int f  = tid + t * 256;
            int ar = f >> 2;
            int aq = f & 3;
            float4 v = *reinterpret_cast<const float4*>(
                &A[(size_t)(rowBase + ar) * K + k0 + aq * 4]);
            As[aq * 4 + 0][ar] = v.x;
            As[aq * 4 + 1][ar] = v.y;
            As[aq * 4 + 2][ar] = v.z;
            As[aq * 4 + 3][ar] = v.w;
        }
        {
            int br = tid >> 4;
            int bc = tid & 15;
            float4 v = *reinterpret_cast<const float4*>(
                &W[(size_t)(k0 + br) * N + colBase + bc * 4]);
            *reinterpret_cast<float4*>(&Bs[br][bc * 4]) = v;
        }
        __syncthreads();

#pragma unroll
        for (int kk = 0; kk < BK; kk++) {
            float4 a0 = *reinterpret_cast<const float4*>(&As[kk][ty * TM]);
            float4 a1 = *reinterpret_cast<const float4*>(&As[kk][ty * TM + 4]);
            float4 b  = *reinterpret_cast<const float4*>(&Bs[kk][tx * TN]);
            float a[TM] = {a0.x, a0.y, a0.z, a0.w, a1.x, a1.y, a1.z, a1.w};
#pragma unroll
            for (int i = 0; i < TM; i++) {
                acc[i][0] += a[i] * b.x;
                acc[i][1] += a[i] * b.y;
                acc[i][2] += a[i] * b.z;
                acc[i][3] += a[i] * b.w;
            }
        }
        __syncthreads();
    }

    float4 bv = *reinterpret_cast<const float4*>(&bias[colBase + tx * TN]);
#pragma unroll
    for (int i = 0; i < TM; i++) {
        int r = rowBase + ty * TM + i;
        float4 o;
        o.x = acc[i][0] + bv.x;
        o.y = acc[i][1] + bv.y;
        o.z = acc[i][2] + bv.z;
        o.w = acc[i][3] + bv.w;
        if (RELU) {
            o.x = fmaxf(o.x, 0.0f); o.y = fmaxf(o.y, 0.0f);
            o.z = fmaxf(o.z, 0.0f); o.w = fmaxf(o.w, 0.0f);
        }
        *reinterpret_cast<float4*>(&C[(size_t)r * N + colBase + tx * TN]) = o;
    }
}

// ------ decoder weight split + transpose: W[K,N] fp32 -> 2x bf16 [N,K] ------
__global__ void wsplit(const float* __restrict__ W, bf16* __restrict__ B0,
                       bf16* __restrict__ B1, int K, int N)
{
    int id = blockIdx.x * 256 + threadIdx.x;
    if (id >= K * N) return;
    int n = id / K, k = id % K;
    bf16 h, m;
    split2(W[(size_t)k * N + n], h, m);
    B0[id] = h; B1[id] = m;
}

// -------- decoder GEMM: mma.sync bf16x2 (hh+hm+mh), analog-only path --------
// CTA 128x128, BK=16. 8 warps (4 M x 2 N), warp tile 32x64.
template <bool RELU>
__global__ __launch_bounds__(256) void mma_gemm(
    const float* __restrict__ A, const bf16* __restrict__ W0,
    const bf16* __restrict__ W1, const float* __restrict__ bias,
    float* __restrict__ C, int M, int N, int K)
{
    __shared__ bf16 As0[128 * 16], As1[128 * 16];
    __shared__ bf16 Bs0[128 * 16], Bs1[128 * 16];

    const int tid  = threadIdx.x;
    const int wid  = tid >> 5;
    const int lane = tid & 31;
    const int g    = lane >> 2;
    const int t    = lane & 3;
    const int mWarp = (wid & 3) * 32;
    const int nWarp = (wid >> 2) * 64;
    const int rowBase = blockIdx.y * 128;
    const int colBase = blockIdx.x * 128;

    float acc[2][8][4];
#pragma unroll
    for (int i = 0; i < 2; i++)
#pragma unroll
        for (int j = 0; j < 8; j++)
#pragma unroll
            for (int q = 0; q < 4; q++) acc[i][j][q] = 0.0f;

    float4 stA[2];
    uint4  stB0, stB1;

    auto ldchunk = [&](int k0) {
#pragma unroll
        for (int tt = 0; tt < 2; tt++) {
            int idx = tid + tt * 256;
            int m = idx >> 2, q = idx & 3;
            stA[tt] = *reinterpret_cast<const float4*>(
                &A[(size_t)(rowBase + m) * K + k0 + q * 4]);
        }
        {
            int n = tid >> 1, kq = tid & 1;
            size_t gi = (size_t)(colBase + n) * K + k0 + kq * 8;
            stB0 = *reinterpret_cast<const uint4*>(&W0[gi]);
            stB1 = *reinterpret_cast<const uint4*>(&W1[gi]);
        }
    };
    auto stchunk = [&]() {
#pragma unroll
        for (int tt = 0; tt < 2; tt++) {
            int idx = tid + tt * 256;
            int m = idx >> 2, q = idx & 3;
            const float* vv = &stA[tt].x;
            bf16 h[4], mm[4];
#pragma unroll
            for (int j = 0; j < 4; j++) split2(vv[j], h[j], mm[j]);
            int o = m * 16 + q * 4;
            *reinterpret_cast<__nv_bfloat162*>(&As0[o])     = {h[0],  h[1]};
            *reinterpret_cast<__nv_bfloat162*>(&As0[o + 2]) = {h[2],  h[3]};
            *reinterpret_cast<__nv_bfloat162*>(&As1[o])     = {mm[0], mm[1]};
            *reinterpret_cast<__nv_bfloat162*>(&As1[o + 2]) = {mm[2], mm[3]};
        }
        {
            int n = tid >> 1, kq = tid & 1;
            int o = n * 16 + kq * 8;
            *reinterpret_cast<uint4*>(&Bs0[o]) = stB0;
            *reinterpret_cast<uint4*>(&Bs1[o]) = stB1;
        }
    };

    ldchunk(0);
    for (int k0 = 0; k0 < K; k0 += 16) {
        stchunk();
        __syncthreads();
        if (k0 + 16 < K) ldchunk(k0 + 16);

        uint32_t aF[2][2][4];
#pragma unroll
        for (int ma = 0; ma < 2; ma++) {
            int m0 = mWarp + ma * 16 + g;
            int b0 = m0 * 16 + 2 * t;
#pragma unroll
            for (int s = 0; s < 2; s++) {
                const bf16* As = (s == 0) ? As0 : As1;
                aF[s][ma][0] = *reinterpret_cast<const uint32_t*>(&As[b0]);
                aF[s][ma][1] = *reinterpret_cast<const uint32_t*>(&As[b0 + 8 * 16]);
                aF[s][ma][2] = *reinterpret_cast<const uint32_t*>(&As[b0 + 8]);
                aF[s][ma][3] = *reinterpret_cast<const uint32_t*>(&As[b0 + 8 * 16 + 8]);
            }
        }
#pragma unroll
        for (int nb = 0; nb < 8; nb++) {
            int n = nWarp + nb * 8 + g;
            int b0 = n * 16 + 2 * t;
            uint32_t bF[2][2];
#pragma unroll
            for (int s = 0; s < 2; s++) {
                const bf16* Bs = (s == 0) ? Bs0 : Bs1;
                bF[s][0] = *reinterpret_cast<const uint32_t*>(&Bs[b0]);
                bF[s][1] = *reinterpret_cast<const uint32_t*>(&Bs[b0 + 8]);
            }
#pragma unroll
            for (int ma = 0; ma < 2; ma++) {
                float* c = acc[ma][nb];
                mma_bf16(c, aF[0][ma], bF[1]);   // h*m  (small first)
                mma_bf16(c, aF[1][ma], bF[0]);   // m*h
                mma_bf16(c, aF[0][ma], bF[0]);   // h*h
            }
        }
        __syncthreads();
    }

#pragma unroll
    for (int ma = 0; ma < 2; ma++) {
        int row0 = rowBase + mWarp + ma * 16 + g;
#pragma unroll
        for (int nb = 0; nb < 8; nb++) {
            int col = colBase + nWarp + nb * 8 + 2 * t;
            float2 bv = *reinterpret_cast<const float2*>(&bias[col]);
            float2 v0, v1;
            v0.x = acc[ma][nb][0] + bv.x;
            v0.y = acc[ma][nb][1] + bv.y;
            v1.x = acc[ma][nb][2] + bv.x;
            v1.y = acc[ma][nb][3] + bv.y;
            if (RELU) {
                v0.x = fmaxf(v0.x, 0.f); v0.y = fmaxf(v0.y, 0.f);
                v1.x = fmaxf(v1.x, 0.f); v1.y = fmaxf(v1.y, 0.f);
            }
            *reinterpret_cast<float2*>(&C[(size_t)row0 * N + col]) = v0;
            *reinterpret_cast<float2*>(&C[(size_t)(row0 + 8) * N + col]) = v1;
        }
    }
}

// ---------------- fused residual quantization (all 4 levels, proven R3) -----
__global__ __launch_bounds__(256) void quant_all(
    const float* __restrict__ z, const float* __restrict__ codebooks,
    float* __restrict__ xq, float* __restrict__ partials)
{
    __shared__ __align__(16) float sC[64 * D3];
    __shared__ float snorm[64];
    __shared__ float sred[256];

    const int tid = threadIdx.x;
    const size_t row = (size_t)blockIdx.x * 256 + tid;

    ull r2[64];
    {
        const ulonglong2* zp = reinterpret_cast<const ulonglong2*>(z + row * D3);
#pragma unroll
        for (int k = 0; k < 32; k++) {
            ulonglong2 v = zp[k];
            r2[2 * k] = v.x; r2[2 * k + 1] = v.y;
        }
    }
    ull mone; PACK2(mone, -1.0f, -1.0f);
    ull ls0 = 0ULL, ls1 = 0ULL;

    for (int l = 0; l < NLEVELS; l++) {
        const float* C = codebooks + (size_t)l * NCODES * D3;
        float best = 3.4e38f;
        int bi = 0;

        for (int ch = 0; ch < 4; ch++) {
            __syncthreads();
            const float4* src =
                reinterpret_cast<const float4*>(C + (size_t)ch * 64 * D3);
            float4* dst = reinterpret_cast<float4*>(sC);
#pragma unroll
            for (int i = 0; i < 8; i++) dst[tid + i * 256] = src[tid + i * 256];
            __syncthreads();
            if (tid < 64) {
                const float4* cp = reinterpret_cast<const float4*>(sC + tid * D3);
                float s = 0.0f;
#pragma unroll
                for (int i = 0; i < 32; i++) {
                    float4 v = cp[i];
                    s += v.x * v.x + v.y * v.y + v.z * v.z + v.w * v.w;
                }
                snorm[tid] = s;
            }
            __syncthreads();

            for (int c = 0; c < 64; c++) {
                const ulonglong2* cp =
                    reinterpret_cast<const ulonglong2*>(sC + c * D3);
                ull a0 = 0ULL, a1 = 0ULL;
#pragma unroll
                for (int k = 0; k < 32; k++) {
                    ulonglong2 v = cp[k];
                    FMA2(a0, r2[2 * k],     v.x);
                    FMA2(a1, r2[2 * k + 1], v.y);
                }
                float s0, s1, s2, s3;
                UNPACK2(s0, s1, a0);
                UNPACK2(s2, s3, a1);
                float dot = (s0 + s1) + (s2 + s3);
                float score = snorm[c] - 2.0f * dot;
                if (score < best) { best = score; bi = ch * 64 + c; }
            }
        }

        const ulonglong2* qp =
            reinterpret_cast<const ulonglong2*>(C + (size_t)bi * D3);
#pragma unroll
        for (int k = 0; k < 32; k++) {
            ulonglong2 q = qp[k];
            ull d0, d1;
            FMA2D(d0, q.x, mone, r2[2 * k]);      // r - q
            FMA2D(d1, q.y, mone, r2[2 * k + 1]);
            FMA2(ls0, d0, d0);
            FMA2(ls1, d1, d1);
            r2[2 * k] = d0; r2[2 * k + 1] = d1;
        }
    }

    {   // x_q = z - r_final
        const ulonglong2* zp = reinterpret_cast<const ulonglong2*>(z + row * D3);
        ulonglong2* xp = reinterpret_cast<ulonglong2*>(xq + row * D3);
#pragma unroll
        for (int k = 0; k < 32; k++) {
            ulonglong2 v = zp[k];
            ulonglong2 o;
            FMA2D(o.x, r2[2 * k],     mone, v.x);
            FMA2D(o.y, r2[2 * k + 1], mone, v.y);
            xp[k] = o;
        }
    }

    float s0, s1, s2, s3;
    UNPACK2(s0, s1, ls0);
    UNPACK2(s2, s3, ls1);
    sred[tid] = (s0 + s1) + (s2 + s3);
    __syncthreads();
#pragma unroll
    for (int s = 128; s > 0; s >>= 1) {
        if (tid < s) sred[tid] += sred[tid + s];
        __syncthreads();
    }
    if (tid == 0) partials[blockIdx.x] = sred[0];
}

__global__ void finalize_loss(const float* __restrict__ partials,
                              float* __restrict__ out)
{
    if (threadIdx.x == 0 && blockIdx.x == 0) {
        float tot = 0.0f;
        for (int i = 0; i < QBLOCKS; i++) tot += partials[i];
        float rq = (1.0f + BETA_F) * tot /
                   ((float)NLEVELS * (float)BATCH * (float)D3);
        *out = rq;
    }
}

// ---------------- launch ----------------
extern "C" void kernel_launch(void* const* d_in, const int* in_sizes, int n_in,
                              void* d_out, int out_size)
{
    (void)in_sizes; (void)n_in;
    const float* x   = (const float*)d_in[0];
    const float* ew0 = (const float*)d_in[1];
    const float* eb0 = (const float*)d_in[2];
    const float* ew1 = (const float*)d_in[3];
    const float* eb1 = (const float*)d_in[4];
    const float* ew2 = (const float*)d_in[5];
    const float* eb2 = (const float*)d_in[6];
    const float* dw0 = (const float*)d_in[7];
    const float* db0 = (const float*)d_in[8];
    const float* dw1 = (const float*)d_in[9];
    const float* db1 = (const float*)d_in[10];
    const float* dw2 = (const float*)d_in[11];
    const float* db2 = (const float*)d_in[12];
    const float* cb  = (const float*)d_in[13];
    float* out = (float*)d_out;

    float *h1, *h2, *z, *xq, *lp;
    bf16 *w0, *w1;
    cudaGetSymbolAddress((void**)&h1, g_h1);
    cudaGetSymbolAddress((void**)&h2, g_h2);
    cudaGetSymbolAddress((void**)&z,  g_z);
    cudaGetSymbolAddress((void**)&xq, g_xq);
    cudaGetSymbolAddress((void**)&lp, g_loss_part);
    cudaGetSymbolAddress((void**)&w0, g_wb0);
    cudaGetSymbolAddress((void**)&w1, g_wb1);

    // decoder weight splits (transposed to [N][K])
    const int offs[3] = {0, 32768, 163840};
    const float* Ws[3] = {dw0, dw1, dw2};
    const int    Ks[3] = {D3, D2, D1};
    const int    Ns[3] = {D2, D1, D0};
    for (int l = 0; l < 3; l++) {
        int total = Ks[l] * Ns[l];
        wsplit<<<(total + 255) / 256, 256>>>(Ws[l], w0 + offs[l], w1 + offs[l],
                                             Ks[l], Ns[l]);
    }

    const int MB = BATCH / 128;

    // encoder: scalar fp32 (flip-safe)
    sgemm_bias<true ><<<dim3(D1 / 64, MB), 256>>>(x,  ew0, eb0, h1, BATCH, D1, D0);
    sgemm_bias<true ><<<dim3(D2 / 64, MB), 256>>>(h1, ew1, eb1, h2, BATCH, D2, D1);
    sgemm_bias<false><<<dim3(D3 / 64, MB), 256>>>(h2, ew2, eb2, z,  BATCH, D3, D2);

    // fused residual quantization
    quant_all<<<QBLOCKS, 256>>>(z, cb, xq, lp);

    // decoder: bf16x2 mma (analog path; y_q == x_q in forward value)
    mma_gemm<true ><<<dim3(D2 / 128, MB), 256>>>(xq, w0 + offs[0], w1 + offs[0], db0, h2,  BATCH, D2, D3);
    mma_gemm<true ><<<dim3(D1 / 128, MB), 256>>>(h2, w0 + offs[1], w1 + offs[1], db1, h1,  BATCH, D1, D2);
    mma_gemm<false><<<dim3(D0 / 128, MB), 256>>>(h1, w0 + offs[2], w1 + offs[2], db2, out, BATCH, D0, D1);

    finalize_loss<<<1, 32>>>(lp, out + (size_t)out_size - 1);
}